// round 7
// baseline (speedup 1.0000x reference)
#include <cuda_runtime.h>
#include <math.h>

#define B_SZ     256
#define S_LEN    1024
#define T_LEN    21
#define NFREQ    11
#define NCH      32
#define COUT     64
#define POOL_T   512
#define HID      32
#define NWROWS   46
#define ROWP2    264     /* conv smem row pitch in u64 */
#define XGT      128     /* rows per CTA in xg GEMM */

#define L2E   1.4426950408889634f
#define TL2E  2.8853900817779268f

typedef unsigned long long u64t;

/* ---------------- device scratch (module-static, no runtime alloc) ------ */
__device__ __align__(16) float g_tw[T_LEN * NFREQ * 2];
__device__ __align__(16) float g_L[NWROWS * T_LEN];
__device__ __align__(16) ulonglong2 g_w01[NCH * 32];
__device__ __align__(16) u64t g_w2v[NCH * 32];
__device__ __align__(16) float g_feat[B_SZ * NCH * S_LEN];
__device__ __align__(16) float g_pooled[B_SZ * POOL_T * COUT];
__device__ __align__(16) float g_xg[B_SZ * POOL_T * 128];

__constant__ float c_lo[8] = {
    -0.010597401784997278f,  0.032883011666982945f,  0.030841381835986965f,
    -0.18703481171888114f,  -0.02798376941698385f,   0.6308807679295904f,
     0.7148465705525415f,    0.23037781330885523f };
__constant__ float c_hi[8] = {
    -0.23037781330885523f,   0.7148465705525415f,   -0.6308807679295904f,
    -0.02798376941698385f,   0.18703481171888114f,   0.030841381835986965f,
    -0.032883011666982945f, -0.010597401784997278f };

/* ---------------- packed f32x2 + fast-math helpers ---------------------- */
static __device__ __forceinline__ u64t pk2(float a, float b) {
    u64t r;
    asm("mov.b64 %0,{%1,%2};" : "=l"(r) : "f"(a), "f"(b));
    return r;
}
static __device__ __forceinline__ void upk2(u64t v, float& a, float& b) {
    asm("mov.b64 {%0,%1},%2;" : "=f"(a), "=f"(b) : "l"(v));
}
static __device__ __forceinline__ void ffma2(u64t& d, u64t a, u64t b) {
    asm("fma.rn.f32x2 %0,%1,%2,%0;" : "+l"(d) : "l"(a), "l"(b));
}
static __device__ __forceinline__ void fadd2(u64t& d, u64t a) {
    asm("add.rn.f32x2 %0,%0,%1;" : "+l"(d) : "l"(a));
}
static __device__ __forceinline__ float ex2f(float x) {
    float r; asm("ex2.approx.f32 %0,%1;" : "=f"(r) : "f"(x)); return r;
}
static __device__ __forceinline__ float rcpf(float x) {
    float r; asm("rcp.approx.f32 %0,%1;" : "=f"(r) : "f"(x)); return r;
}
static __device__ __forceinline__ float sig_p(float zp) {   /* z pre-scaled L2E  */
    return rcpf(1.f + ex2f(-zp));
}
static __device__ __forceinline__ float tanh_p(float zp) {  /* z pre-scaled 2L2E */
    return fmaf(2.f, rcpf(1.f + ex2f(-zp)), -1.f);
}

/* ============ K0: twiddles, wavelet map L, paired conv weights =========== */
__global__ void precompute_kernel(const float* __restrict__ conv_w)
{
    int tid = threadIdx.x;

    for (int i = tid; i < T_LEN * NFREQ; i += blockDim.x) {
        int n = i / NFREQ, k = i % NFREQ;
        double ang = 2.0 * (double)(k * n) / 21.0;
        g_tw[2 * i]     = (float)cospi(ang);
        g_tw[2 * i + 1] = (float)(-sinpi(ang));
    }

    if (tid < T_LEN) {
        float a[21];
        #pragma unroll
        for (int i = 0; i < 21; i++) a[i] = (i == tid) ? 1.f : 0.f;
        int n = 21;
        const int rowbase[4] = {32, 22, 14, 7};
        for (int lev = 0; lev < 4; lev++) {
            int mout = (n + 5) / 2 + 1;
            float cA[14];
            for (int m = 0; m < mout; m++) {
                float aL = 0.f, aH = 0.f;
                #pragma unroll
                for (int j = 0; j < 8; j++) {
                    int idx = 2 * m + 1 - j;
                    if (idx < 0)  idx = -idx - 1;
                    if (idx >= n) idx = 2 * n - 1 - idx;
                    aL += c_lo[j] * a[idx];
                    aH += c_hi[j] * a[idx];
                }
                cA[m] = aL;
                g_L[(rowbase[lev] + m) * T_LEN + tid] = aH;
            }
            for (int m = 0; m < mout; m++) a[m] = cA[m];
            n = mout;
        }
        for (int m = 0; m < n; m++)
            g_L[m * T_LEN + tid] = a[m];
    }
    __syncthreads();

    for (int idx = tid; idx < NCH * 32; idx += blockDim.x) {
        int ci = idx >> 5, cp = idx & 31;
        float vlo[3], vhi[3];
        #pragma unroll
        for (int k = 0; k < 3; k++) {
            float a = conv_w[(cp * 78 + ci) * 3 + k];
            float b = conv_w[((cp + 32) * 78 + ci) * 3 + k];
            if (ci < T_LEN) {
                for (int j = 0; j < NWROWS; j++) {
                    float l = g_L[j * T_LEN + ci];
                    a += conv_w[(cp * 78 + 32 + j) * 3 + k] * l;
                    b += conv_w[((cp + 32) * 78 + 32 + j) * 3 + k] * l;
                }
            }
            vlo[k] = a; vhi[k] = b;
        }
        ulonglong2 w01;
        w01.x = pk2(vlo[0], vhi[0]);
        w01.y = pk2(vlo[1], vhi[1]);
        g_w01[idx] = w01;
        g_w2v[idx] = pk2(vlo[2], vhi[2]);
    }
}

/* ============ K1: feat[b][ch][s] = [x(21), |rfft|(11)] =================== */
__global__ void __launch_bounds__(128) feat_kernel(const float* __restrict__ x)
{
    __shared__ float sx[128 * T_LEN];
    __shared__ float stw[T_LEN * NFREQ * 2];

    int b  = blockIdx.x >> 3;
    int s0 = (blockIdx.x & 7) << 7;
    int tid = threadIdx.x;

    for (int i = tid; i < 128 * T_LEN; i += 128)
        sx[i] = x[(size_t)(b * S_LEN + s0) * T_LEN + i];
    for (int i = tid; i < T_LEN * NFREQ * 2; i += 128)
        stw[i] = g_tw[i];
    __syncthreads();

    float xr[T_LEN];
    #pragma unroll
    for (int i = 0; i < T_LEN; i++) xr[i] = sx[tid * T_LEN + i];

    int s = s0 + tid;
    float* fb = g_feat + (size_t)b * NCH * S_LEN + s;
    #pragma unroll
    for (int i = 0; i < T_LEN; i++) fb[i * S_LEN] = xr[i];

    for (int k = 0; k < NFREQ; k++) {
        float re = 0.f, im = 0.f;
        #pragma unroll
        for (int n = 0; n < T_LEN; n++) {
            float cw = stw[(n * NFREQ + k) * 2];
            float sw = stw[(n * NFREQ + k) * 2 + 1];
            re = fmaf(xr[n], cw, re);
            im = fmaf(xr[n], sw, im);
        }
        fb[(T_LEN + k) * S_LEN] = sqrtf(re * re + im * im);
    }
}

/* ============ K2: conv3 + ReLU + maxpool2, FFMA2 channel pairs =========== */
__global__ void __launch_bounds__(512) conv_pool2_kernel(const float* __restrict__ conv_b)
{
    extern __shared__ u64t sm2[];
    u64t*       sdup = sm2;
    ulonglong2* sw01 = (ulonglong2*)(sm2 + NCH * ROWP2);
    u64t*       sw2v = (u64t*)(sw01 + NCH * 32);

    int tid = threadIdx.x;
    int b   = blockIdx.x >> 2;
    int s0  = (blockIdx.x & 3) * 256;
    int cp  = tid & 31;
    int sg  = tid >> 5;
    int cs  = sg * 16;

    const float* fb = g_feat + (size_t)b * NCH * S_LEN;
    for (int i = tid; i < NCH * 258; i += 512) {
        int ci = i / 258, col = i % 258;
        int s = s0 + col - 1;
        float v = (s >= 0 && s < S_LEN) ? fb[ci * S_LEN + s] : 0.f;
        sdup[ci * ROWP2 + col] = pk2(v, v);
    }
    for (int i = tid; i < NCH * 32; i += 512) {
        sw01[i] = g_w01[i];
        sw2v[i] = g_w2v[i];
    }
    __syncthreads();

    u64t bias2 = pk2(conv_b[cp], conv_b[cp + 32]);
    u64t acc[16];
    #pragma unroll
    for (int i = 0; i < 16; i++) acc[i] = bias2;

    for (int ci = 0; ci < NCH; ci++) {
        const ulonglong2* vp = (const ulonglong2*)(sdup + ci * ROWP2 + cs);
        ulonglong2 w01 = sw01[ci * 32 + cp];
        u64t       wk2 = sw2v[ci * 32 + cp];
        u64t v[18];
        #pragma unroll
        for (int q = 0; q < 9; q++) {
            ulonglong2 t2 = vp[q];
            v[2 * q] = t2.x; v[2 * q + 1] = t2.y;
        }
        #pragma unroll
        for (int i = 0; i < 16; i++) {
            ffma2(acc[i], w01.x, v[i]);
            ffma2(acc[i], w01.y, v[i + 1]);
            ffma2(acc[i], wk2,   v[i + 2]);
        }
    }

    float* pout = g_pooled + (size_t)b * POOL_T * COUT;
    int t0 = (s0 + cs) >> 1;
    #pragma unroll
    for (int i = 0; i < 8; i++) {
        float l0, h0, l1, h1;
        upk2(acc[2 * i],     l0, h0);
        upk2(acc[2 * i + 1], l1, h1);
        pout[(t0 + i) * COUT + cp]      = fmaxf(fmaxf(l0, l1), 0.f);
        pout[(t0 + i) * COUT + cp + 32] = fmaxf(fmaxf(h0, h1), 0.f);
    }
}

/* ============ K2b: xg = pooled @ Wcol + bias, gate-prescaled ============= */
__global__ void __launch_bounds__(256) xg2_kernel(
    const float* __restrict__ w_ih, const float* __restrict__ b_ih,
    const float* __restrict__ b_hh)
{
    extern __shared__ u64t smw[];
    u64t*  sW = smw;
    float* sA = (float*)(smw + 64 * 66);

    int tid = threadIdx.x;
    size_t R0 = (size_t)blockIdx.x * XGT;

    for (int idx = tid; idx < 64 * 64; idx += 256) {
        int k = idx >> 6, cp = idx & 63;
        int j = cp >> 1, g0 = (cp & 1) * 2;
        float s0f = (cp & 1) ? TL2E : L2E;
        sW[k * 66 + cp] = pk2(w_ih[(g0 * 32 + j) * 64 + k] * s0f,
                              w_ih[((g0 + 1) * 32 + j) * 64 + k] * L2E);
    }

    const float* Ap = g_pooled + R0 * 64;
    for (int idx = tid; idx < XGT * 16; idx += 256) {
        int r = idx >> 4, q = idx & 15;
        float4 v = *(const float4*)(Ap + r * 64 + q * 4);
        sA[(4 * q + 0) * 132 + r] = v.x;
        sA[(4 * q + 1) * 132 + r] = v.y;
        sA[(4 * q + 2) * 132 + r] = v.z;
        sA[(4 * q + 3) * 132 + r] = v.w;
    }
    __syncthreads();

    int tx = tid & 15, ty = tid >> 4;
    int r0 = ty * 8;

    u64t acc[8][4];
    #pragma unroll
    for (int i = 0; i < 8; i++)
        #pragma unroll
        for (int q = 0; q < 4; q++) acc[i][q] = 0ull;

    #pragma unroll 4
    for (int k = 0; k < 64; k++) {
        const float* ar = sA + k * 132 + r0;
        float4 av0 = *(const float4*)ar;
        float4 av1 = *(const float4*)(ar + 4);
        u64t ad[8] = { pk2(av0.x, av0.x), pk2(av0.y, av0.y),
                       pk2(av0.z, av0.z), pk2(av0.w, av0.w),
                       pk2(av1.x, av1.x), pk2(av1.y, av1.y),
                       pk2(av1.z, av1.z), pk2(av1.w, av1.w) };
        const u64t* wr = sW + k * 66 + tx;
        u64t wv[4] = { wr[0], wr[16], wr[32], wr[48] };
        #pragma unroll
        for (int i = 0; i < 8; i++)
            #pragma unroll
            for (int q = 0; q < 4; q++)
                ffma2(acc[i][q], ad[i], wv[q]);
    }

    float* outp = g_xg + R0 * 128;
    #pragma unroll
    for (int q = 0; q < 4; q++) {
        int cp = tx + q * 16;
        int j = cp >> 1, g0 = (cp & 1) * 2;
        int gi0 = g0 * 32 + j, gi1 = (g0 + 1) * 32 + j;
        float s0f = (cp & 1) ? TL2E : L2E;
        u64t bp = pk2((b_ih[gi0] + b_hh[gi0]) * s0f,
                      (b_ih[gi1] + b_hh[gi1]) * L2E);
        #pragma unroll
        for (int i = 0; i < 8; i++) {
            u64t s = acc[i][q];
            fadd2(s, bp);
            float lo, hi;
            upk2(s, lo, hi);
            *(float2*)(outp + (size_t)(r0 + i) * 128 + cp * 2) = make_float2(lo, hi);
        }
    }
}

/* ============ K3: LSTM v7 — 1 warp = 2 independent batches =============== */
/* Two recurrence chains interleave in one warp: chain bubbles of batch A    */
/* are filled by batch B. Weights shared (one register copy).                */
struct LState {
    float c, h;
    ulonglong2 pre[2];
};

static __device__ __forceinline__ void lstm_step(
    const u64t (&w2)[4][16], const float* hbuf_in, float* hbuf_out,
    ulonglong2 z4, float& c, float& h)
{
    const ulonglong2* hp = (const ulonglong2*)hbuf_in;

    u64t a0 = z4.x & 0xffffffffull, a1 = z4.x >> 32;
    u64t a2 = z4.y & 0xffffffffull, a3 = z4.y >> 32;
    u64t d0 = 0, d1 = 0, d2 = 0, d3 = 0;

    #pragma unroll
    for (int kq = 0; kq < 8; kq++) {
        ulonglong2 h2 = hp[kq];
        ffma2(a0, w2[0][2 * kq],     h2.x);
        ffma2(a1, w2[1][2 * kq],     h2.x);
        ffma2(a2, w2[2][2 * kq],     h2.x);
        ffma2(a3, w2[3][2 * kq],     h2.x);
        ffma2(d0, w2[0][2 * kq + 1], h2.y);
        ffma2(d1, w2[1][2 * kq + 1], h2.y);
        ffma2(d2, w2[2][2 * kq + 1], h2.y);
        ffma2(d3, w2[3][2 * kq + 1], h2.y);
    }
    fadd2(a0, d0); fadd2(a1, d1); fadd2(a2, d2); fadd2(a3, d3);

    float lo, hi;
    upk2(a0, lo, hi); float zi = lo + hi;
    upk2(a1, lo, hi); float zf = lo + hi;
    upk2(a2, lo, hi); float zg = lo + hi;
    upk2(a3, lo, hi); float zo = lo + hi;

    float ai = sig_p(zi), af = sig_p(zf);
    float ag = tanh_p(zg), ao = sig_p(zo);
    c = fmaf(af, c, ai * ag);
    h = ao * tanh_p(c * TL2E);
    *hbuf_out = h;
}

__global__ void __launch_bounds__(32) lstm7_kernel(
    const float* __restrict__ w_hh, const float* __restrict__ fc_w,
    const float* __restrict__ fc_b, float* __restrict__ out)
{
    __shared__ __align__(16) float s_hA[2][32];
    __shared__ __align__(16) float s_hB[2][32];

    int j  = threadIdx.x;
    int bA = blockIdx.x;
    int bB = blockIdx.x + 128;

    const float sc[4] = { L2E, L2E, TL2E, L2E };
    u64t w2[4][16];
    #pragma unroll
    for (int g = 0; g < 4; g++) {
        const float4* row = (const float4*)(w_hh + (g * 32 + j) * 32);
        #pragma unroll
        for (int q = 0; q < 8; q++) {
            float4 v = row[q];
            w2[g][2 * q]     = pk2(v.x * sc[g], v.y * sc[g]);
            w2[g][2 * q + 1] = pk2(v.z * sc[g], v.w * sc[g]);
        }
    }

    s_hA[0][j] = 0.f;
    s_hB[0][j] = 0.f;
    float cA = 0.f, hA = 0.f, cB = 0.f, hB = 0.f;

    const ulonglong2* xpA = (const ulonglong2*)(g_xg + (size_t)bA * POOL_T * 128);
    const ulonglong2* xpB = (const ulonglong2*)(g_xg + (size_t)bB * POOL_T * 128);
    ulonglong2 preA[2], preB[2];
    #pragma unroll
    for (int u = 0; u < 2; u++) {
        preA[u] = xpA[u * 32 + j];
        preB[u] = xpB[u * 32 + j];
    }
    __syncwarp();

    for (int t = 0; t < POOL_T; t += 2) {
        #pragma unroll
        for (int u = 0; u < 2; u++) {
            int tt = t + u;
            ulonglong2 zA = preA[u];
            ulonglong2 zB = preB[u];
            int tn = tt + 2;
            if (tn > POOL_T - 1) tn = POOL_T - 1;
            preA[u] = xpA[(size_t)tn * 32 + j];
            preB[u] = xpB[(size_t)tn * 32 + j];

            int cur = tt & 1, nxt = cur ^ 1;
            lstm_step(w2, s_hA[cur], &s_hA[nxt][j], zA, cA, hA);
            lstm_step(w2, s_hB[cur], &s_hB[nxt][j], zB, cB, hB);
            __syncwarp();
        }
    }

    float vA = fc_w[j] * hA;
    float vB = fc_w[j] * hB;
    #pragma unroll
    for (int off = 16; off; off >>= 1) {
        vA += __shfl_down_sync(0xffffffffu, vA, off);
        vB += __shfl_down_sync(0xffffffffu, vB, off);
    }
    if (j == 0) {
        out[bA] = vA + fc_b[0];
        out[bB] = vB + fc_b[0];
    }
}

/* ======================================================================== */
extern "C" void kernel_launch(void* const* d_in, const int* in_sizes, int n_in,
                              void* d_out, int out_size)
{
    const float* x      = (const float*)d_in[0];
    const float* conv_w = (const float*)d_in[1];
    const float* conv_b = (const float*)d_in[2];
    const float* w_ih   = (const float*)d_in[3];
    const float* w_hh   = (const float*)d_in[4];
    const float* b_ih   = (const float*)d_in[5];
    const float* b_hh   = (const float*)d_in[6];
    const float* fc_w   = (const float*)d_in[7];
    const float* fc_b   = (const float*)d_in[8];
    float* out = (float*)d_out;

    precompute_kernel<<<1, 256>>>(conv_w);
    feat_kernel<<<B_SZ * 8, 128>>>(x);

    size_t smem_c = (size_t)NCH * ROWP2 * 8 + (size_t)NCH * 32 * 24;
    cudaFuncSetAttribute(conv_pool2_kernel,
                         cudaFuncAttributeMaxDynamicSharedMemorySize, (int)smem_c);
    conv_pool2_kernel<<<B_SZ * 4, 512, smem_c>>>(conv_b);

    size_t smem_g = (size_t)(64 * 66) * sizeof(u64t) +
                    (size_t)(64 * 132) * sizeof(float);
    cudaFuncSetAttribute(xg2_kernel,
                         cudaFuncAttributeMaxDynamicSharedMemorySize, (int)smem_g);
    xg2_kernel<<<(B_SZ * POOL_T) / XGT, 256, smem_g>>>(w_ih, b_ih, b_hh);

    lstm7_kernel<<<B_SZ / 2, 32>>>(w_hh, fc_w, fc_b, out);
}

// round 8
// speedup vs baseline: 1.4035x; 1.4035x over previous
#include <cuda_runtime.h>
#include <math.h>

#define B_SZ     256
#define S_LEN    1024
#define T_LEN    21
#define NFREQ    11
#define NCH      32
#define COUT     64
#define POOL_T   512
#define HID      32
#define NWROWS   46
#define ROWP2    264     /* conv smem row pitch in u64 */
#define FROWP    132     /* sP pitch in floats */

#define L2E   1.4426950408889634f
#define TL2E  2.8853900817779268f

typedef unsigned long long u64t;

/* ---------------- device scratch (module-static, no runtime alloc) ------ */
__device__ __align__(16) float g_tw[T_LEN * NFREQ * 2];
__device__ __align__(16) float g_L[NWROWS * T_LEN];
__device__ __align__(16) ulonglong2 g_w01[NCH * 32];
__device__ __align__(16) u64t g_w2v[NCH * 32];
__device__ __align__(16) float g_xg[B_SZ * POOL_T * 128];

__constant__ float c_lo[8] = {
    -0.010597401784997278f,  0.032883011666982945f,  0.030841381835986965f,
    -0.18703481171888114f,  -0.02798376941698385f,   0.6308807679295904f,
     0.7148465705525415f,    0.23037781330885523f };
__constant__ float c_hi[8] = {
    -0.23037781330885523f,   0.7148465705525415f,   -0.6308807679295904f,
    -0.02798376941698385f,   0.18703481171888114f,   0.030841381835986965f,
    -0.032883011666982945f, -0.010597401784997278f };

/* ---------------- packed f32x2 + fast-math helpers ---------------------- */
static __device__ __forceinline__ u64t pk2(float a, float b) {
    u64t r;
    asm("mov.b64 %0,{%1,%2};" : "=l"(r) : "f"(a), "f"(b));
    return r;
}
static __device__ __forceinline__ void upk2(u64t v, float& a, float& b) {
    asm("mov.b64 {%0,%1},%2;" : "=f"(a), "=f"(b) : "l"(v));
}
static __device__ __forceinline__ void ffma2(u64t& d, u64t a, u64t b) {
    asm("fma.rn.f32x2 %0,%1,%2,%0;" : "+l"(d) : "l"(a), "l"(b));
}
static __device__ __forceinline__ void fadd2(u64t& d, u64t a) {
    asm("add.rn.f32x2 %0,%0,%1;" : "+l"(d) : "l"(a));
}
static __device__ __forceinline__ float ex2f(float x) {
    float r; asm("ex2.approx.f32 %0,%1;" : "=f"(r) : "f"(x)); return r;
}
static __device__ __forceinline__ float rcpf(float x) {
    float r; asm("rcp.approx.f32 %0,%1;" : "=f"(r) : "f"(x)); return r;
}
static __device__ __forceinline__ float sig_p(float zp) {   /* z pre-scaled L2E  */
    return rcpf(1.f + ex2f(-zp));
}
static __device__ __forceinline__ float tanh_p(float zp) {  /* z pre-scaled 2L2E */
    return fmaf(-2.f, rcpf(1.f + ex2f(zp)), 1.f);
}

/* ============ K0: twiddles, wavelet map L, paired conv weights =========== */
__global__ void precompute_kernel(const float* __restrict__ conv_w)
{
    int tid = threadIdx.x;

    for (int i = tid; i < T_LEN * NFREQ; i += blockDim.x) {
        int n = i / NFREQ, k = i % NFREQ;
        double ang = 2.0 * (double)(k * n) / 21.0;
        g_tw[2 * i]     = (float)cospi(ang);
        g_tw[2 * i + 1] = (float)(-sinpi(ang));
    }

    if (tid < T_LEN) {
        float a[21];
        #pragma unroll
        for (int i = 0; i < 21; i++) a[i] = (i == tid) ? 1.f : 0.f;
        int n = 21;
        const int rowbase[4] = {32, 22, 14, 7};
        for (int lev = 0; lev < 4; lev++) {
            int mout = (n + 5) / 2 + 1;
            float cA[14];
            for (int m = 0; m < mout; m++) {
                float aL = 0.f, aH = 0.f;
                #pragma unroll
                for (int j = 0; j < 8; j++) {
                    int idx = 2 * m + 1 - j;
                    if (idx < 0)  idx = -idx - 1;
                    if (idx >= n) idx = 2 * n - 1 - idx;
                    aL += c_lo[j] * a[idx];
                    aH += c_hi[j] * a[idx];
                }
                cA[m] = aL;
                g_L[(rowbase[lev] + m) * T_LEN + tid] = aH;
            }
            for (int m = 0; m < mout; m++) a[m] = cA[m];
            n = mout;
        }
        for (int m = 0; m < n; m++)
            g_L[m * T_LEN + tid] = a[m];
    }
    __syncthreads();

    for (int idx = tid; idx < NCH * 32; idx += blockDim.x) {
        int ci = idx >> 5, cp = idx & 31;
        float vlo[3], vhi[3];
        #pragma unroll
        for (int k = 0; k < 3; k++) {
            float a = conv_w[(cp * 78 + ci) * 3 + k];
            float b = conv_w[((cp + 32) * 78 + ci) * 3 + k];
            if (ci < T_LEN) {
                for (int j = 0; j < NWROWS; j++) {
                    float l = g_L[j * T_LEN + ci];
                    a += conv_w[(cp * 78 + 32 + j) * 3 + k] * l;
                    b += conv_w[((cp + 32) * 78 + 32 + j) * 3 + k] * l;
                }
            }
            vlo[k] = a; vhi[k] = b;
        }
        ulonglong2 w01;
        w01.x = pk2(vlo[0], vhi[0]);
        w01.y = pk2(vlo[1], vhi[1]);
        g_w01[idx] = w01;
        g_w2v[idx] = pk2(vlo[2], vhi[2]);
    }
}

/* ============ K1: fused feat(DFT) + conv3/ReLU/maxpool2 + xg GEMM ======== */
/* smem layout (u64 units):
   sdup [0, 8448)            : 32ch x 264 dup-pair input tile
   sw01 [8448, 10496)        : conv taps k0,k1 (ulonglong2 x 1024)
   sw2v [10496, 11520)       : conv tap k2
   sW   [11520, 15744)       : xg weights [k=64][pitch 66] gate-pairs
   sP   [15744, 19968)       : pooled tile as floats [k=64][pitch 132]
   stw  [19968, 20200)       : DFT twiddles (462 floats)                    */
#define SM_SW01  8448
#define SM_SW2V  10496
#define SM_SW    11520
#define SM_SP    15744
#define SM_STW   19968
#define SM_TOTAL_U64 20200

__global__ void __launch_bounds__(512) fused_kernel(
    const float* __restrict__ x,   const float* __restrict__ conv_b,
    const float* __restrict__ w_ih, const float* __restrict__ b_ih,
    const float* __restrict__ b_hh)
{
    extern __shared__ u64t sm[];
    u64t*       sdup = sm;
    ulonglong2* sw01 = (ulonglong2*)(sm + SM_SW01);
    u64t*       sw2v = sm + SM_SW2V;
    u64t*       sW   = sm + SM_SW;
    float*      sP   = (float*)(sm + SM_SP);
    float*      stw  = (float*)(sm + SM_STW);

    int tid = threadIdx.x;
    int b   = blockIdx.x >> 2;
    int q   = blockIdx.x & 3;
    int s0  = q * 256;

    /* ---- phase 0: stage all weights/twiddles ---- */
    for (int i = tid; i < NCH * 32; i += 512) {
        sw01[i] = g_w01[i];
        sw2v[i] = g_w2v[i];
    }
    for (int i = tid; i < T_LEN * NFREQ * 2; i += 512)
        stw[i] = g_tw[i];
    for (int idx = tid; idx < 64 * 64; idx += 512) {
        int k = idx >> 6, cp = idx & 63;
        int j = cp >> 1, g0 = (cp & 1) * 2;
        float s0f = (cp & 1) ? TL2E : L2E;
        sW[k * 66 + cp] = pk2(w_ih[(g0 * 32 + j) * 64 + k] * s0f,
                              w_ih[((g0 + 1) * 32 + j) * 64 + k] * L2E);
    }
    __syncthreads();

    /* ---- phase 1: features (raw + |rfft|) into sdup ---- */
    if (tid < 258) {
        int s = s0 + tid - 1;
        if (s >= 0 && s < S_LEN) {
            const float* xp = x + (size_t)(b * S_LEN + s) * T_LEN;
            float xr[T_LEN];
            #pragma unroll
            for (int i = 0; i < T_LEN; i++) xr[i] = xp[i];
            #pragma unroll
            for (int i = 0; i < T_LEN; i++)
                sdup[i * ROWP2 + tid] = pk2(xr[i], xr[i]);
            for (int k = 0; k < NFREQ; k++) {
                float re = 0.f, im = 0.f;
                #pragma unroll
                for (int n = 0; n < T_LEN; n++) {
                    re = fmaf(xr[n], stw[(n * NFREQ + k) * 2],     re);
                    im = fmaf(xr[n], stw[(n * NFREQ + k) * 2 + 1], im);
                }
                float m = sqrtf(re * re + im * im);
                sdup[(T_LEN + k) * ROWP2 + tid] = pk2(m, m);
            }
        } else {
            #pragma unroll
            for (int ci = 0; ci < NCH; ci++)
                sdup[ci * ROWP2 + tid] = 0ull;
        }
    }
    __syncthreads();

    /* ---- phase 2: conv3 + ReLU + maxpool2 -> sP[k][t] (transposed) ---- */
    {
        int cp = tid & 31;
        int sg = tid >> 5;
        int cs = sg * 16;

        u64t bias2 = pk2(conv_b[cp], conv_b[cp + 32]);
        u64t acc[16];
        #pragma unroll
        for (int i = 0; i < 16; i++) acc[i] = bias2;

        for (int ci = 0; ci < NCH; ci++) {
            const ulonglong2* vp = (const ulonglong2*)(sdup + ci * ROWP2 + cs);
            ulonglong2 w01 = sw01[ci * 32 + cp];
            u64t       wk2 = sw2v[ci * 32 + cp];
            u64t v[18];
            #pragma unroll
            for (int qq = 0; qq < 9; qq++) {
                ulonglong2 t2 = vp[qq];
                v[2 * qq] = t2.x; v[2 * qq + 1] = t2.y;
            }
            #pragma unroll
            for (int i = 0; i < 16; i++) {
                ffma2(acc[i], w01.x, v[i]);
                ffma2(acc[i], w01.y, v[i + 1]);
                ffma2(acc[i], wk2,   v[i + 2]);
            }
        }

        int t0l = sg * 8;
        #pragma unroll
        for (int i = 0; i < 8; i++) {
            float l0, h0, l1, h1;
            upk2(acc[2 * i],     l0, h0);
            upk2(acc[2 * i + 1], l1, h1);
            sP[cp * FROWP + t0l + i]        = fmaxf(fmaxf(l0, l1), 0.f);
            sP[(cp + 32) * FROWP + t0l + i] = fmaxf(fmaxf(h0, h1), 0.f);
        }
    }
    __syncthreads();

    /* ---- phase 3: xg GEMM (256 threads), gate-prescaled + bias ---- */
    if (tid < 256) {
        int tx = tid & 15, ty = tid >> 4;
        int r0 = ty * 8;

        u64t acc[8][4];
        #pragma unroll
        for (int i = 0; i < 8; i++)
            #pragma unroll
            for (int qq = 0; qq < 4; qq++) acc[i][qq] = 0ull;

        #pragma unroll 4
        for (int k = 0; k < 64; k++) {
            const float* ar = sP + k * FROWP + r0;
            float4 av0 = *(const float4*)ar;
            float4 av1 = *(const float4*)(ar + 4);
            u64t ad[8] = { pk2(av0.x, av0.x), pk2(av0.y, av0.y),
                           pk2(av0.z, av0.z), pk2(av0.w, av0.w),
                           pk2(av1.x, av1.x), pk2(av1.y, av1.y),
                           pk2(av1.z, av1.z), pk2(av1.w, av1.w) };
            const u64t* wr = sW + k * 66 + tx;
            u64t wv[4] = { wr[0], wr[16], wr[32], wr[48] };
            #pragma unroll
            for (int i = 0; i < 8; i++)
                #pragma unroll
                for (int qq = 0; qq < 4; qq++)
                    ffma2(acc[i][qq], ad[i], wv[qq]);
        }

        float* outp = g_xg + ((size_t)b * POOL_T + q * 128) * 128;
        #pragma unroll
        for (int qq = 0; qq < 4; qq++) {
            int cp = tx + qq * 16;
            int j = cp >> 1, g0 = (cp & 1) * 2;
            int gi0 = g0 * 32 + j, gi1 = (g0 + 1) * 32 + j;
            float s0f = (cp & 1) ? TL2E : L2E;
            u64t bp = pk2((b_ih[gi0] + b_hh[gi0]) * s0f,
                          (b_ih[gi1] + b_hh[gi1]) * L2E);
            #pragma unroll
            for (int i = 0; i < 8; i++) {
                u64t s = acc[i][qq];
                fadd2(s, bp);
                float lo, hi;
                upk2(s, lo, hi);
                *(float2*)(outp + (size_t)(r0 + i) * 128 + cp * 2) = make_float2(lo, hi);
            }
        }
    }
}

/* ============ K3: LSTM v5 (reverted: best known recurrence) ============== */
__global__ void __launch_bounds__(64) lstm5_kernel(
    const float* __restrict__ w_hh, const float* __restrict__ fc_w,
    const float* __restrict__ fc_b, float* __restrict__ out)
{
    __shared__ __align__(16) float s_h[2][2][32];   /* [warp][buf][j] */

    int w = threadIdx.x >> 5;
    int j = threadIdx.x & 31;
    int b = blockIdx.x * 2 + w;

    const float sc[4] = { L2E, L2E, TL2E, L2E };
    u64t w2[4][16];
    #pragma unroll
    for (int g = 0; g < 4; g++) {
        const float4* row = (const float4*)(w_hh + (g * 32 + j) * 32);
        #pragma unroll
        for (int q = 0; q < 8; q++) {
            float4 v = row[q];
            w2[g][2 * q]     = pk2(v.x * sc[g], v.y * sc[g]);
            w2[g][2 * q + 1] = pk2(v.z * sc[g], v.w * sc[g]);
        }
    }

    s_h[w][0][j] = 0.f;
    float c = 0.f, h = 0.f;

    const ulonglong2* xgp = (const ulonglong2*)(g_xg + (size_t)b * POOL_T * 128);
    ulonglong2 pre[4];
    #pragma unroll
    for (int u = 0; u < 4; u++) pre[u] = xgp[u * 32 + j];
    __syncwarp();

    for (int t = 0; t < POOL_T; t += 4) {
        #pragma unroll
        for (int u = 0; u < 4; u++) {
            int tt = t + u;
            ulonglong2 z4 = pre[u];
            int tn = tt + 4;
            if (tn > POOL_T - 1) tn = POOL_T - 1;
            pre[u] = xgp[(size_t)tn * 32 + j];

            const ulonglong2* hp = (const ulonglong2*)s_h[w][tt & 1];

            u64t a0 = z4.x & 0xffffffffull, a1 = z4.x >> 32;
            u64t a2 = z4.y & 0xffffffffull, a3 = z4.y >> 32;
            u64t b0 = 0, b1 = 0, b2 = 0, b3 = 0;
            u64t d0 = 0, d1 = 0, d2 = 0, d3 = 0;
            u64t e0 = 0, e1 = 0, e2 = 0, e3 = 0;

            #pragma unroll
            for (int kq = 0; kq < 4; kq++) {
                ulonglong2 h2 = hp[kq];
                ffma2(a0, w2[0][2 * kq], h2.x);
                ffma2(a1, w2[1][2 * kq], h2.x);
                ffma2(a2, w2[2][2 * kq], h2.x);
                ffma2(a3, w2[3][2 * kq], h2.x);
                ffma2(d0, w2[0][2 * kq + 1], h2.y);
                ffma2(d1, w2[1][2 * kq + 1], h2.y);
                ffma2(d2, w2[2][2 * kq + 1], h2.y);
                ffma2(d3, w2[3][2 * kq + 1], h2.y);
            }
            #pragma unroll
            for (int kq = 4; kq < 8; kq++) {
                ulonglong2 h2 = hp[kq];
                ffma2(b0, w2[0][2 * kq], h2.x);
                ffma2(b1, w2[1][2 * kq], h2.x);
                ffma2(b2, w2[2][2 * kq], h2.x);
                ffma2(b3, w2[3][2 * kq], h2.x);
                ffma2(e0, w2[0][2 * kq + 1], h2.y);
                ffma2(e1, w2[1][2 * kq + 1], h2.y);
                ffma2(e2, w2[2][2 * kq + 1], h2.y);
                ffma2(e3, w2[3][2 * kq + 1], h2.y);
            }
            fadd2(a0, b0); fadd2(d0, e0); fadd2(a0, d0);
            fadd2(a1, b1); fadd2(d1, e1); fadd2(a1, d1);
            fadd2(a2, b2); fadd2(d2, e2); fadd2(a2, d2);
            fadd2(a3, b3); fadd2(d3, e3); fadd2(a3, d3);

            float lo, hi;
            upk2(a0, lo, hi); float zi = lo + hi;
            upk2(a1, lo, hi); float zf = lo + hi;
            upk2(a2, lo, hi); float zg = lo + hi;
            upk2(a3, lo, hi); float zo = lo + hi;

            float ai = sig_p(zi), af = sig_p(zf);
            float ag = tanh_p(zg), ao = sig_p(zo);
            c = fmaf(af, c, ai * ag);
            h = ao * tanh_p(c * TL2E);

            s_h[w][(tt & 1) ^ 1][j] = h;
            __syncwarp();
        }
    }

    float v = fc_w[j] * h;
    #pragma unroll
    for (int off = 16; off; off >>= 1)
        v += __shfl_down_sync(0xffffffffu, v, off);
    if (j == 0) out[b] = v + fc_b[0];
}

/* ======================================================================== */
extern "C" void kernel_launch(void* const* d_in, const int* in_sizes, int n_in,
                              void* d_out, int out_size)
{
    const float* x      = (const float*)d_in[0];
    const float* conv_w = (const float*)d_in[1];
    const float* conv_b = (const float*)d_in[2];
    const float* w_ih   = (const float*)d_in[3];
    const float* w_hh   = (const float*)d_in[4];
    const float* b_ih   = (const float*)d_in[5];
    const float* b_hh   = (const float*)d_in[6];
    const float* fc_w   = (const float*)d_in[7];
    const float* fc_b   = (const float*)d_in[8];
    float* out = (float*)d_out;

    precompute_kernel<<<1, 256>>>(conv_w);

    size_t smem_f = (size_t)SM_TOTAL_U64 * sizeof(u64t);
    cudaFuncSetAttribute(fused_kernel,
                         cudaFuncAttributeMaxDynamicSharedMemorySize, (int)smem_f);
    fused_kernel<<<B_SZ * 4, 512, smem_f>>>(x, conv_b, w_ih, b_ih, b_hh);

    lstm5_kernel<<<B_SZ / 2, 64>>>(w_hh, fc_w, fc_b, out);
}

// round 9
// speedup vs baseline: 1.4807x; 1.0550x over previous
#include <cuda_runtime.h>
#include <math.h>

#define B_SZ     256
#define S_LEN    1024
#define T_LEN    21
#define NFREQ    11
#define NCH      32
#define COUT     64
#define POOL_T   512
#define HID      32
#define NWROWS   46
#define ROWP2    264     /* conv smem row pitch in u64 */
#define FROWP    132     /* sP pitch in floats */

#define L2E   1.4426950408889634f
#define TL2E  2.8853900817779268f

typedef unsigned long long u64t;

/* ---------------- device scratch (module-static, no runtime alloc) ------ */
__device__ __align__(16) float g_tw[T_LEN * NFREQ * 2];
__device__ __align__(16) float g_L[NWROWS * T_LEN];
__device__ __align__(16) ulonglong2 g_w01[NCH * 32];
__device__ __align__(16) u64t g_w2v[NCH * 32];
__device__ __align__(16) float g_xg[B_SZ * POOL_T * 128];

__constant__ float c_lo[8] = {
    -0.010597401784997278f,  0.032883011666982945f,  0.030841381835986965f,
    -0.18703481171888114f,  -0.02798376941698385f,   0.6308807679295904f,
     0.7148465705525415f,    0.23037781330885523f };
__constant__ float c_hi[8] = {
    -0.23037781330885523f,   0.7148465705525415f,   -0.6308807679295904f,
    -0.02798376941698385f,   0.18703481171888114f,   0.030841381835986965f,
    -0.032883011666982945f, -0.010597401784997278f };

/* ---------------- packed f32x2 + fast-math helpers ---------------------- */
static __device__ __forceinline__ u64t pk2(float a, float b) {
    u64t r;
    asm("mov.b64 %0,{%1,%2};" : "=l"(r) : "f"(a), "f"(b));
    return r;
}
static __device__ __forceinline__ void upk2(u64t v, float& a, float& b) {
    asm("mov.b64 {%0,%1},%2;" : "=f"(a), "=f"(b) : "l"(v));
}
static __device__ __forceinline__ void ffma2(u64t& d, u64t a, u64t b) {
    asm("fma.rn.f32x2 %0,%1,%2,%0;" : "+l"(d) : "l"(a), "l"(b));
}
static __device__ __forceinline__ void fadd2(u64t& d, u64t a) {
    asm("add.rn.f32x2 %0,%0,%1;" : "+l"(d) : "l"(a));
}
static __device__ __forceinline__ float ex2f(float x) {
    float r; asm("ex2.approx.f32 %0,%1;" : "=f"(r) : "f"(x)); return r;
}
static __device__ __forceinline__ float rcpf(float x) {
    float r; asm("rcp.approx.f32 %0,%1;" : "=f"(r) : "f"(x)); return r;
}
static __device__ __forceinline__ float sig_p(float zp) {
    return rcpf(1.f + ex2f(-zp));
}
static __device__ __forceinline__ float tanh_p(float zp) {
    return fmaf(-2.f, rcpf(1.f + ex2f(zp)), 1.f);
}

/* ============ K0a: twiddles + wavelet linear map L (tiny, 1 block) ======= */
__global__ void precompute_L_kernel()
{
    int tid = threadIdx.x;

    for (int i = tid; i < T_LEN * NFREQ; i += blockDim.x) {
        int n = i / NFREQ, k = i % NFREQ;
        double ang = 2.0 * (double)(k * n) / 21.0;
        g_tw[2 * i]     = (float)cospi(ang);
        g_tw[2 * i + 1] = (float)(-sinpi(ang));
    }

    if (tid < T_LEN) {
        float a[21];
        #pragma unroll
        for (int i = 0; i < 21; i++) a[i] = (i == tid) ? 1.f : 0.f;
        int n = 21;
        const int rowbase[4] = {32, 22, 14, 7};
        for (int lev = 0; lev < 4; lev++) {
            int mout = (n + 5) / 2 + 1;
            float cA[14];
            for (int m = 0; m < mout; m++) {
                float aL = 0.f, aH = 0.f;
                #pragma unroll
                for (int j = 0; j < 8; j++) {
                    int idx = 2 * m + 1 - j;
                    if (idx < 0)  idx = -idx - 1;
                    if (idx >= n) idx = 2 * n - 1 - idx;
                    aL += c_lo[j] * a[idx];
                    aH += c_hi[j] * a[idx];
                }
                cA[m] = aL;
                g_L[(rowbase[lev] + m) * T_LEN + tid] = aH;
            }
            for (int m = 0; m < mout; m++) a[m] = cA[m];
            n = mout;
        }
        for (int m = 0; m < n; m++)
            g_L[m * T_LEN + tid] = a[m];
    }
}

/* ============ K0b: weight fold, grid 32 (ci) x 32 threads (cp) =========== */
__global__ void __launch_bounds__(32) precompute_fold_kernel(
    const float* __restrict__ conv_w)
{
    __shared__ float sL[NWROWS];

    int ci = blockIdx.x;
    int cp = threadIdx.x;

    if (ci < T_LEN) {
        for (int j = cp; j < NWROWS; j += 32)
            sL[j] = g_L[j * T_LEN + ci];
    }
    __syncwarp();

    float vlo[3], vhi[3];
    #pragma unroll
    for (int k = 0; k < 3; k++) {
        vlo[k] = conv_w[(cp * 78 + ci) * 3 + k];
        vhi[k] = conv_w[((cp + 32) * 78 + ci) * 3 + k];
    }
    if (ci < T_LEN) {
        const float* wl = conv_w + (cp * 78 + 32) * 3;
        const float* wh = conv_w + ((cp + 32) * 78 + 32) * 3;
        #pragma unroll 2
        for (int j = 0; j < NWROWS; j++) {
            float l = sL[j];
            #pragma unroll
            for (int k = 0; k < 3; k++) {
                vlo[k] = fmaf(wl[j * 3 + k], l, vlo[k]);
                vhi[k] = fmaf(wh[j * 3 + k], l, vhi[k]);
            }
        }
    }
    ulonglong2 w01;
    w01.x = pk2(vlo[0], vhi[0]);
    w01.y = pk2(vlo[1], vhi[1]);
    g_w01[ci * 32 + cp] = w01;
    g_w2v[ci * 32 + cp] = pk2(vlo[2], vhi[2]);
}

/* ============ K1: fused feat(DFT) + conv3/ReLU/maxpool2 + xg GEMM ======== */
#define SM_SW01  8448
#define SM_SW2V  10496
#define SM_SW    11520
#define SM_SP    15744
#define SM_STW   19968
#define SM_TOTAL_U64 20200

__global__ void __launch_bounds__(512) fused_kernel(
    const float* __restrict__ x,   const float* __restrict__ conv_b,
    const float* __restrict__ w_ih, const float* __restrict__ b_ih,
    const float* __restrict__ b_hh)
{
    extern __shared__ u64t sm[];
    u64t*       sdup = sm;
    ulonglong2* sw01 = (ulonglong2*)(sm + SM_SW01);
    u64t*       sw2v = sm + SM_SW2V;
    u64t*       sW   = sm + SM_SW;
    float*      sP   = (float*)(sm + SM_SP);
    float*      stw  = (float*)(sm + SM_STW);

    int tid = threadIdx.x;
    int b   = blockIdx.x >> 2;
    int q   = blockIdx.x & 3;
    int s0  = q * 256;

    /* ---- phase 0: stage all weights/twiddles ---- */
    for (int i = tid; i < NCH * 32; i += 512) {
        sw01[i] = g_w01[i];
        sw2v[i] = g_w2v[i];
    }
    for (int i = tid; i < T_LEN * NFREQ * 2; i += 512)
        stw[i] = g_tw[i];
    for (int idx = tid; idx < 64 * 64; idx += 512) {
        int k = idx >> 6, cp = idx & 63;
        int j = cp >> 1, g0 = (cp & 1) * 2;
        float s0f = (cp & 1) ? TL2E : L2E;
        sW[k * 66 + cp] = pk2(w_ih[(g0 * 32 + j) * 64 + k] * s0f,
                              w_ih[((g0 + 1) * 32 + j) * 64 + k] * L2E);
    }
    __syncthreads();

    /* ---- phase 1: features (raw + |rfft|) into sdup ---- */
    if (tid < 258) {
        int s = s0 + tid - 1;
        if (s >= 0 && s < S_LEN) {
            const float* xp = x + (size_t)(b * S_LEN + s) * T_LEN;
            float xr[T_LEN];
            #pragma unroll
            for (int i = 0; i < T_LEN; i++) xr[i] = xp[i];
            #pragma unroll
            for (int i = 0; i < T_LEN; i++)
                sdup[i * ROWP2 + tid] = pk2(xr[i], xr[i]);
            for (int k = 0; k < NFREQ; k++) {
                float re = 0.f, im = 0.f;
                #pragma unroll
                for (int n = 0; n < T_LEN; n++) {
                    re = fmaf(xr[n], stw[(n * NFREQ + k) * 2],     re);
                    im = fmaf(xr[n], stw[(n * NFREQ + k) * 2 + 1], im);
                }
                float m = sqrtf(re * re + im * im);
                sdup[(T_LEN + k) * ROWP2 + tid] = pk2(m, m);
            }
        } else {
            #pragma unroll
            for (int ci = 0; ci < NCH; ci++)
                sdup[ci * ROWP2 + tid] = 0ull;
        }
    }
    __syncthreads();

    /* ---- phase 2: conv3 + ReLU + maxpool2 -> sP[k][t] (transposed) ---- */
    {
        int cp = tid & 31;
        int sg = tid >> 5;
        int cs = sg * 16;

        u64t bias2 = pk2(conv_b[cp], conv_b[cp + 32]);
        u64t acc[16];
        #pragma unroll
        for (int i = 0; i < 16; i++) acc[i] = bias2;

        for (int ci = 0; ci < NCH; ci++) {
            const ulonglong2* vp = (const ulonglong2*)(sdup + ci * ROWP2 + cs);
            ulonglong2 w01 = sw01[ci * 32 + cp];
            u64t       wk2 = sw2v[ci * 32 + cp];
            u64t v[18];
            #pragma unroll
            for (int qq = 0; qq < 9; qq++) {
                ulonglong2 t2 = vp[qq];
                v[2 * qq] = t2.x; v[2 * qq + 1] = t2.y;
            }
            #pragma unroll
            for (int i = 0; i < 16; i++) {
                ffma2(acc[i], w01.x, v[i]);
                ffma2(acc[i], w01.y, v[i + 1]);
                ffma2(acc[i], wk2,   v[i + 2]);
            }
        }

        int t0l = sg * 8;
        #pragma unroll
        for (int i = 0; i < 8; i++) {
            float l0, h0, l1, h1;
            upk2(acc[2 * i],     l0, h0);
            upk2(acc[2 * i + 1], l1, h1);
            sP[cp * FROWP + t0l + i]        = fmaxf(fmaxf(l0, l1), 0.f);
            sP[(cp + 32) * FROWP + t0l + i] = fmaxf(fmaxf(h0, h1), 0.f);
        }
    }
    __syncthreads();

    /* ---- phase 3: xg GEMM, all 512 threads (4-row x 4-colpair tiles) --- */
    {
        int tx = tid & 15, ty = tid >> 4;   /* ty 0..31 */
        int r0 = ty * 4;

        u64t acc[4][4];
        #pragma unroll
        for (int i = 0; i < 4; i++)
            #pragma unroll
            for (int qq = 0; qq < 4; qq++) acc[i][qq] = 0ull;

        #pragma unroll 4
        for (int k = 0; k < 64; k++) {
            const float* ar = sP + k * FROWP + r0;
            float4 av0 = *(const float4*)ar;
            u64t ad[4] = { pk2(av0.x, av0.x), pk2(av0.y, av0.y),
                           pk2(av0.z, av0.z), pk2(av0.w, av0.w) };
            const u64t* wr = sW + k * 66 + tx;
            u64t wv[4] = { wr[0], wr[16], wr[32], wr[48] };
            #pragma unroll
            for (int i = 0; i < 4; i++)
                #pragma unroll
                for (int qq = 0; qq < 4; qq++)
                    ffma2(acc[i][qq], ad[i], wv[qq]);
        }

        float* outp = g_xg + ((size_t)b * POOL_T + q * 128) * 128;
        #pragma unroll
        for (int qq = 0; qq < 4; qq++) {
            int cp = tx + qq * 16;
            int j = cp >> 1, g0 = (cp & 1) * 2;
            int gi0 = g0 * 32 + j, gi1 = (g0 + 1) * 32 + j;
            float s0f = (cp & 1) ? TL2E : L2E;
            u64t bp = pk2((b_ih[gi0] + b_hh[gi0]) * s0f,
                          (b_ih[gi1] + b_hh[gi1]) * L2E);
            #pragma unroll
            for (int i = 0; i < 4; i++) {
                u64t s = acc[i][qq];
                fadd2(s, bp);
                float lo, hi;
                upk2(s, lo, hi);
                *(float2*)(outp + (size_t)(r0 + i) * 128 + cp * 2) = make_float2(lo, hi);
            }
        }
    }
}

/* ============ K3: LSTM v5 (best known recurrence) ======================== */
__global__ void __launch_bounds__(64) lstm5_kernel(
    const float* __restrict__ w_hh, const float* __restrict__ fc_w,
    const float* __restrict__ fc_b, float* __restrict__ out)
{
    __shared__ __align__(16) float s_h[2][2][32];

    int w = threadIdx.x >> 5;
    int j = threadIdx.x & 31;
    int b = blockIdx.x * 2 + w;

    const float sc[4] = { L2E, L2E, TL2E, L2E };
    u64t w2[4][16];
    #pragma unroll
    for (int g = 0; g < 4; g++) {
        const float4* row = (const float4*)(w_hh + (g * 32 + j) * 32);
        #pragma unroll
        for (int q = 0; q < 8; q++) {
            float4 v = row[q];
            w2[g][2 * q]     = pk2(v.x * sc[g], v.y * sc[g]);
            w2[g][2 * q + 1] = pk2(v.z * sc[g], v.w * sc[g]);
        }
    }

    s_h[w][0][j] = 0.f;
    float c = 0.f, h = 0.f;

    const ulonglong2* xgp = (const ulonglong2*)(g_xg + (size_t)b * POOL_T * 128);
    ulonglong2 pre[4];
    #pragma unroll
    for (int u = 0; u < 4; u++) pre[u] = xgp[u * 32 + j];
    __syncwarp();

    for (int t = 0; t < POOL_T; t += 4) {
        #pragma unroll
        for (int u = 0; u < 4; u++) {
            int tt = t + u;
            ulonglong2 z4 = pre[u];
            int tn = tt + 4;
            if (tn > POOL_T - 1) tn = POOL_T - 1;
            pre[u] = xgp[(size_t)tn * 32 + j];

            const ulonglong2* hp = (const ulonglong2*)s_h[w][tt & 1];

            u64t a0 = z4.x & 0xffffffffull, a1 = z4.x >> 32;
            u64t a2 = z4.y & 0xffffffffull, a3 = z4.y >> 32;
            u64t b0 = 0, b1 = 0, b2 = 0, b3 = 0;
            u64t d0 = 0, d1 = 0, d2 = 0, d3 = 0;
            u64t e0 = 0, e1 = 0, e2 = 0, e3 = 0;

            #pragma unroll
            for (int kq = 0; kq < 4; kq++) {
                ulonglong2 h2 = hp[kq];
                ffma2(a0, w2[0][2 * kq], h2.x);
                ffma2(a1, w2[1][2 * kq], h2.x);
                ffma2(a2, w2[2][2 * kq], h2.x);
                ffma2(a3, w2[3][2 * kq], h2.x);
                ffma2(d0, w2[0][2 * kq + 1], h2.y);
                ffma2(d1, w2[1][2 * kq + 1], h2.y);
                ffma2(d2, w2[2][2 * kq + 1], h2.y);
                ffma2(d3, w2[3][2 * kq + 1], h2.y);
            }
            #pragma unroll
            for (int kq = 4; kq < 8; kq++) {
                ulonglong2 h2 = hp[kq];
                ffma2(b0, w2[0][2 * kq], h2.x);
                ffma2(b1, w2[1][2 * kq], h2.x);
                ffma2(b2, w2[2][2 * kq], h2.x);
                ffma2(b3, w2[3][2 * kq], h2.x);
                ffma2(e0, w2[0][2 * kq + 1], h2.y);
                ffma2(e1, w2[1][2 * kq + 1], h2.y);
                ffma2(e2, w2[2][2 * kq + 1], h2.y);
                ffma2(e3, w2[3][2 * kq + 1], h2.y);
            }
            fadd2(a0, b0); fadd2(d0, e0); fadd2(a0, d0);
            fadd2(a1, b1); fadd2(d1, e1); fadd2(a1, d1);
            fadd2(a2, b2); fadd2(d2, e2); fadd2(a2, d2);
            fadd2(a3, b3); fadd2(d3, e3); fadd2(a3, d3);

            float lo, hi;
            upk2(a0, lo, hi); float zi = lo + hi;
            upk2(a1, lo, hi); float zf = lo + hi;
            upk2(a2, lo, hi); float zg = lo + hi;
            upk2(a3, lo, hi); float zo = lo + hi;

            float ai = sig_p(zi), af = sig_p(zf);
            float ag = tanh_p(zg), ao = sig_p(zo);
            c = fmaf(af, c, ai * ag);
            h = ao * tanh_p(c * TL2E);

            s_h[w][(tt & 1) ^ 1][j] = h;
            __syncwarp();
        }
    }

    float v = fc_w[j] * h;
    #pragma unroll
    for (int off = 16; off; off >>= 1)
        v += __shfl_down_sync(0xffffffffu, v, off);
    if (j == 0) out[b] = v + fc_b[0];
}

/* ======================================================================== */
extern "C" void kernel_launch(void* const* d_in, const int* in_sizes, int n_in,
                              void* d_out, int out_size)
{
    const float* x      = (const float*)d_in[0];
    const float* conv_w = (const float*)d_in[1];
    const float* conv_b = (const float*)d_in[2];
    const float* w_ih   = (const float*)d_in[3];
    const float* w_hh   = (const float*)d_in[4];
    const float* b_ih   = (const float*)d_in[5];
    const float* b_hh   = (const float*)d_in[6];
    const float* fc_w   = (const float*)d_in[7];
    const float* fc_b   = (const float*)d_in[8];
    float* out = (float*)d_out;

    precompute_L_kernel<<<1, 64>>>();
    precompute_fold_kernel<<<NCH, 32>>>(conv_w);

    size_t smem_f = (size_t)SM_TOTAL_U64 * sizeof(u64t);
    cudaFuncSetAttribute(fused_kernel,
                         cudaFuncAttributeMaxDynamicSharedMemorySize, (int)smem_f);
    fused_kernel<<<B_SZ * 4, 512, smem_f>>>(x, conv_b, w_ih, b_ih, b_hh);

    lstm5_kernel<<<B_SZ / 2, 64>>>(w_hh, fc_w, fc_b, out);
}

// round 10
// speedup vs baseline: 1.4971x; 1.0110x over previous
#include <cuda_runtime.h>
#include <math.h>

#define B_SZ     256
#define S_LEN    1024
#define T_LEN    21
#define NFREQ    11
#define NCH      32
#define COUT     64
#define POOL_T   512
#define HID      32
#define NWROWS   46
#define ROWP2    264     /* conv smem row pitch in u64 */
#define FROWP    132     /* sP pitch in floats */

#define L2E    1.4426950408889634f
#define TL2E   2.8853900817779268f
#define TL2E2  5.7707801635558537f   /* 2 * TL2E */

typedef unsigned long long u64t;

/* ---------------- device scratch (module-static, no runtime alloc) ------ */
__device__ __align__(16) float g_tw[T_LEN * NFREQ * 2];
__device__ __align__(16) float g_L[NWROWS * T_LEN];
__device__ __align__(16) ulonglong2 g_w01[NCH * 32];
__device__ __align__(16) u64t g_w2v[NCH * 32];
__device__ __align__(16) float g_xg[B_SZ * POOL_T * 128];

__constant__ float c_lo[8] = {
    -0.010597401784997278f,  0.032883011666982945f,  0.030841381835986965f,
    -0.18703481171888114f,  -0.02798376941698385f,   0.6308807679295904f,
     0.7148465705525415f,    0.23037781330885523f };
__constant__ float c_hi[8] = {
    -0.23037781330885523f,   0.7148465705525415f,   -0.6308807679295904f,
    -0.02798376941698385f,   0.18703481171888114f,   0.030841381835986965f,
    -0.032883011666982945f, -0.010597401784997278f };

/* ---------------- packed f32x2 + fast-math helpers ---------------------- */
static __device__ __forceinline__ u64t pk2(float a, float b) {
    u64t r;
    asm("mov.b64 %0,{%1,%2};" : "=l"(r) : "f"(a), "f"(b));
    return r;
}
static __device__ __forceinline__ void upk2(u64t v, float& a, float& b) {
    asm("mov.b64 {%0,%1},%2;" : "=f"(a), "=f"(b) : "l"(v));
}
static __device__ __forceinline__ void ffma2(u64t& d, u64t a, u64t b) {
    asm("fma.rn.f32x2 %0,%1,%2,%0;" : "+l"(d) : "l"(a), "l"(b));
}
static __device__ __forceinline__ void fadd2(u64t& d, u64t a) {
    asm("add.rn.f32x2 %0,%0,%1;" : "+l"(d) : "l"(a));
}
static __device__ __forceinline__ float ex2f(float x) {
    float r; asm("ex2.approx.f32 %0,%1;" : "=f"(r) : "f"(x)); return r;
}
static __device__ __forceinline__ float rcpf(float x) {
    float r; asm("rcp.approx.f32 %0,%1;" : "=f"(r) : "f"(x)); return r;
}
static __device__ __forceinline__ float sig_p(float zp) {   /* z pre-scaled L2E */
    return rcpf(1.f + ex2f(-zp));
}

/* ============ K0a: twiddles + wavelet linear map L (tiny, 1 block) ======= */
__global__ void precompute_L_kernel()
{
    int tid = threadIdx.x;

    for (int i = tid; i < T_LEN * NFREQ; i += blockDim.x) {
        int n = i / NFREQ, k = i % NFREQ;
        double ang = 2.0 * (double)(k * n) / 21.0;
        g_tw[2 * i]     = (float)cospi(ang);
        g_tw[2 * i + 1] = (float)(-sinpi(ang));
    }

    if (tid < T_LEN) {
        float a[21];
        #pragma unroll
        for (int i = 0; i < 21; i++) a[i] = (i == tid) ? 1.f : 0.f;
        int n = 21;
        const int rowbase[4] = {32, 22, 14, 7};
        for (int lev = 0; lev < 4; lev++) {
            int mout = (n + 5) / 2 + 1;
            float cA[14];
            for (int m = 0; m < mout; m++) {
                float aL = 0.f, aH = 0.f;
                #pragma unroll
                for (int j = 0; j < 8; j++) {
                    int idx = 2 * m + 1 - j;
                    if (idx < 0)  idx = -idx - 1;
                    if (idx >= n) idx = 2 * n - 1 - idx;
                    aL += c_lo[j] * a[idx];
                    aH += c_hi[j] * a[idx];
                }
                cA[m] = aL;
                g_L[(rowbase[lev] + m) * T_LEN + tid] = aH;
            }
            for (int m = 0; m < mout; m++) a[m] = cA[m];
            n = mout;
        }
        for (int m = 0; m < n; m++)
            g_L[m * T_LEN + tid] = a[m];
    }
}

/* ============ K0b: weight fold, grid 32 (ci) x 32 threads (cp) =========== */
__global__ void __launch_bounds__(32) precompute_fold_kernel(
    const float* __restrict__ conv_w)
{
    __shared__ float sL[NWROWS];

    int ci = blockIdx.x;
    int cp = threadIdx.x;

    if (ci < T_LEN) {
        for (int j = cp; j < NWROWS; j += 32)
            sL[j] = g_L[j * T_LEN + ci];
    }
    __syncwarp();

    float vlo[3], vhi[3];
    #pragma unroll
    for (int k = 0; k < 3; k++) {
        vlo[k] = conv_w[(cp * 78 + ci) * 3 + k];
        vhi[k] = conv_w[((cp + 32) * 78 + ci) * 3 + k];
    }
    if (ci < T_LEN) {
        const float* wl = conv_w + (cp * 78 + 32) * 3;
        const float* wh = conv_w + ((cp + 32) * 78 + 32) * 3;
        #pragma unroll 2
        for (int j = 0; j < NWROWS; j++) {
            float l = sL[j];
            #pragma unroll
            for (int k = 0; k < 3; k++) {
                vlo[k] = fmaf(wl[j * 3 + k], l, vlo[k]);
                vhi[k] = fmaf(wh[j * 3 + k], l, vhi[k]);
            }
        }
    }
    ulonglong2 w01;
    w01.x = pk2(vlo[0], vhi[0]);
    w01.y = pk2(vlo[1], vhi[1]);
    g_w01[ci * 32 + cp] = w01;
    g_w2v[ci * 32 + cp] = pk2(vlo[2], vhi[2]);
}

/* ============ K1: fused feat(DFT) + conv3/ReLU/maxpool2 + xg GEMM ======== */
#define SM_SW01  8448
#define SM_SW2V  10496
#define SM_SW    11520
#define SM_SP    15744
#define SM_STW   19968
#define SM_TOTAL_U64 20200

__global__ void __launch_bounds__(512) fused_kernel(
    const float* __restrict__ x,   const float* __restrict__ conv_b,
    const float* __restrict__ w_ih, const float* __restrict__ b_ih,
    const float* __restrict__ b_hh)
{
    extern __shared__ u64t sm[];
    u64t*       sdup = sm;
    ulonglong2* sw01 = (ulonglong2*)(sm + SM_SW01);
    u64t*       sw2v = sm + SM_SW2V;
    u64t*       sW   = sm + SM_SW;
    float*      sP   = (float*)(sm + SM_SP);
    float*      stw  = (float*)(sm + SM_STW);

    int tid = threadIdx.x;
    int b   = blockIdx.x >> 2;
    int q   = blockIdx.x & 3;
    int s0  = q * 256;

    /* ---- phase 0: stage all weights/twiddles ---- */
    for (int i = tid; i < NCH * 32; i += 512) {
        sw01[i] = g_w01[i];
        sw2v[i] = g_w2v[i];
    }
    for (int i = tid; i < T_LEN * NFREQ * 2; i += 512)
        stw[i] = g_tw[i];
    for (int idx = tid; idx < 64 * 64; idx += 512) {
        int k = idx >> 6, cp = idx & 63;
        int j = cp >> 1, g0 = (cp & 1) * 2;
        float s0f = (cp & 1) ? TL2E : L2E;
        sW[k * 66 + cp] = pk2(w_ih[(g0 * 32 + j) * 64 + k] * s0f,
                              w_ih[((g0 + 1) * 32 + j) * 64 + k] * L2E);
    }
    __syncthreads();

    /* ---- phase 1: features (raw + |rfft|) into sdup ---- */
    if (tid < 258) {
        int s = s0 + tid - 1;
        if (s >= 0 && s < S_LEN) {
            const float* xp = x + (size_t)(b * S_LEN + s) * T_LEN;
            float xr[T_LEN];
            #pragma unroll
            for (int i = 0; i < T_LEN; i++) xr[i] = xp[i];
            #pragma unroll
            for (int i = 0; i < T_LEN; i++)
                sdup[i * ROWP2 + tid] = pk2(xr[i], xr[i]);
            for (int k = 0; k < NFREQ; k++) {
                float re = 0.f, im = 0.f;
                #pragma unroll
                for (int n = 0; n < T_LEN; n++) {
                    re = fmaf(xr[n], stw[(n * NFREQ + k) * 2],     re);
                    im = fmaf(xr[n], stw[(n * NFREQ + k) * 2 + 1], im);
                }
                float m = sqrtf(re * re + im * im);
                sdup[(T_LEN + k) * ROWP2 + tid] = pk2(m, m);
            }
        } else {
            #pragma unroll
            for (int ci = 0; ci < NCH; ci++)
                sdup[ci * ROWP2 + tid] = 0ull;
        }
    }
    __syncthreads();

    /* ---- phase 2: conv3 + ReLU + maxpool2 -> sP[k][t] (transposed) ---- */
    {
        int cp = tid & 31;
        int sg = tid >> 5;
        int cs = sg * 16;

        u64t bias2 = pk2(conv_b[cp], conv_b[cp + 32]);
        u64t acc[16];
        #pragma unroll
        for (int i = 0; i < 16; i++) acc[i] = bias2;

        for (int ci = 0; ci < NCH; ci++) {
            const ulonglong2* vp = (const ulonglong2*)(sdup + ci * ROWP2 + cs);
            ulonglong2 w01 = sw01[ci * 32 + cp];
            u64t       wk2 = sw2v[ci * 32 + cp];
            u64t v[18];
            #pragma unroll
            for (int qq = 0; qq < 9; qq++) {
                ulonglong2 t2 = vp[qq];
                v[2 * qq] = t2.x; v[2 * qq + 1] = t2.y;
            }
            #pragma unroll
            for (int i = 0; i < 16; i++) {
                ffma2(acc[i], w01.x, v[i]);
                ffma2(acc[i], w01.y, v[i + 1]);
                ffma2(acc[i], wk2,   v[i + 2]);
            }
        }

        int t0l = sg * 8;
        #pragma unroll
        for (int i = 0; i < 8; i++) {
            float l0, h0, l1, h1;
            upk2(acc[2 * i],     l0, h0);
            upk2(acc[2 * i + 1], l1, h1);
            sP[cp * FROWP + t0l + i]        = fmaxf(fmaxf(l0, l1), 0.f);
            sP[(cp + 32) * FROWP + t0l + i] = fmaxf(fmaxf(h0, h1), 0.f);
        }
    }
    __syncthreads();

    /* ---- phase 3: xg GEMM, 256 threads, 8-row x 4-colpair tiles -------- */
    if (tid < 256) {
        int tx = tid & 15, ty = tid >> 4;
        int r0 = ty * 8;

        u64t acc[8][4];
        #pragma unroll
        for (int i = 0; i < 8; i++)
            #pragma unroll
            for (int qq = 0; qq < 4; qq++) acc[i][qq] = 0ull;

        #pragma unroll 4
        for (int k = 0; k < 64; k++) {
            const float* ar = sP + k * FROWP + r0;
            float4 av0 = *(const float4*)ar;
            float4 av1 = *(const float4*)(ar + 4);
            u64t ad[8] = { pk2(av0.x, av0.x), pk2(av0.y, av0.y),
                           pk2(av0.z, av0.z), pk2(av0.w, av0.w),
                           pk2(av1.x, av1.x), pk2(av1.y, av1.y),
                           pk2(av1.z, av1.z), pk2(av1.w, av1.w) };
            const u64t* wr = sW + k * 66 + tx;
            u64t wv[4] = { wr[0], wr[16], wr[32], wr[48] };
            #pragma unroll
            for (int i = 0; i < 8; i++)
                #pragma unroll
                for (int qq = 0; qq < 4; qq++)
                    ffma2(acc[i][qq], ad[i], wv[qq]);
        }

        float* outp = g_xg + ((size_t)b * POOL_T + q * 128) * 128;
        #pragma unroll
        for (int qq = 0; qq < 4; qq++) {
            int cp = tx + qq * 16;
            int j = cp >> 1, g0 = (cp & 1) * 2;
            int gi0 = g0 * 32 + j, gi1 = (g0 + 1) * 32 + j;
            float s0f = (cp & 1) ? TL2E : L2E;
            u64t bp = pk2((b_ih[gi0] + b_hh[gi0]) * s0f,
                          (b_ih[gi1] + b_hh[gi1]) * L2E);
            #pragma unroll
            for (int i = 0; i < 8; i++) {
                u64t s = acc[i][qq];
                fadd2(s, bp);
                float lo, hi;
                upk2(s, lo, hi);
                *(float2*)(outp + (size_t)(r0 + i) * 128 + cp * 2) = make_float2(lo, hi);
            }
        }
    }
}

/* ============ K3: LSTM v5.1 — TL2E folded into c recurrence ============== */
/* c register stores c' = TL2E * c_true; g activation pre-scaled by TL2E.   */
__global__ void __launch_bounds__(64) lstm5_kernel(
    const float* __restrict__ w_hh, const float* __restrict__ fc_w,
    const float* __restrict__ fc_b, float* __restrict__ out)
{
    __shared__ __align__(16) float s_h[2][2][32];

    int w = threadIdx.x >> 5;
    int j = threadIdx.x & 31;
    int b = blockIdx.x * 2 + w;

    const float sc[4] = { L2E, L2E, TL2E, L2E };
    u64t w2[4][16];
    #pragma unroll
    for (int g = 0; g < 4; g++) {
        const float4* row = (const float4*)(w_hh + (g * 32 + j) * 32);
        #pragma unroll
        for (int q = 0; q < 8; q++) {
            float4 v = row[q];
            w2[g][2 * q]     = pk2(v.x * sc[g], v.y * sc[g]);
            w2[g][2 * q + 1] = pk2(v.z * sc[g], v.w * sc[g]);
        }
    }

    s_h[w][0][j] = 0.f;
    float c = 0.f, h = 0.f;

    const ulonglong2* xgp = (const ulonglong2*)(g_xg + (size_t)b * POOL_T * 128);
    ulonglong2 pre[4];
    #pragma unroll
    for (int u = 0; u < 4; u++) pre[u] = xgp[u * 32 + j];
    __syncwarp();

    for (int t = 0; t < POOL_T; t += 4) {
        #pragma unroll
        for (int u = 0; u < 4; u++) {
            int tt = t + u;
            ulonglong2 z4 = pre[u];
            int tn = tt + 4;
            if (tn > POOL_T - 1) tn = POOL_T - 1;
            pre[u] = xgp[(size_t)tn * 32 + j];

            const ulonglong2* hp = (const ulonglong2*)s_h[w][tt & 1];

            u64t a0 = z4.x & 0xffffffffull, a1 = z4.x >> 32;
            u64t a2 = z4.y & 0xffffffffull, a3 = z4.y >> 32;
            u64t b0 = 0, b1 = 0, b2 = 0, b3 = 0;
            u64t d0 = 0, d1 = 0, d2 = 0, d3 = 0;
            u64t e0 = 0, e1 = 0, e2 = 0, e3 = 0;

            #pragma unroll
            for (int kq = 0; kq < 4; kq++) {
                ulonglong2 h2 = hp[kq];
                ffma2(a0, w2[0][2 * kq], h2.x);
                ffma2(a1, w2[1][2 * kq], h2.x);
                ffma2(a2, w2[2][2 * kq], h2.x);
                ffma2(a3, w2[3][2 * kq], h2.x);
                ffma2(d0, w2[0][2 * kq + 1], h2.y);
                ffma2(d1, w2[1][2 * kq + 1], h2.y);
                ffma2(d2, w2[2][2 * kq + 1], h2.y);
                ffma2(d3, w2[3][2 * kq + 1], h2.y);
            }
            #pragma unroll
            for (int kq = 4; kq < 8; kq++) {
                ulonglong2 h2 = hp[kq];
                ffma2(b0, w2[0][2 * kq], h2.x);
                ffma2(b1, w2[1][2 * kq], h2.x);
                ffma2(b2, w2[2][2 * kq], h2.x);
                ffma2(b3, w2[3][2 * kq], h2.x);
                ffma2(e0, w2[0][2 * kq + 1], h2.y);
                ffma2(e1, w2[1][2 * kq + 1], h2.y);
                ffma2(e2, w2[2][2 * kq + 1], h2.y);
                ffma2(e3, w2[3][2 * kq + 1], h2.y);
            }
            fadd2(a0, b0); fadd2(d0, e0); fadd2(a0, d0);
            fadd2(a1, b1); fadd2(d1, e1); fadd2(a1, d1);
            fadd2(a2, b2); fadd2(d2, e2); fadd2(a2, d2);
            fadd2(a3, b3); fadd2(d3, e3); fadd2(a3, d3);

            float lo, hi;
            upk2(a0, lo, hi); float zi = lo + hi;
            upk2(a1, lo, hi); float zf = lo + hi;
            upk2(a2, lo, hi); float zg = lo + hi;
            upk2(a3, lo, hi); float zo = lo + hi;

            float ai = sig_p(zi), af = sig_p(zf);
            float ao = sig_p(zo);
            /* g activation pre-scaled by TL2E: agS = TL2E * tanh(zg_true) */
            float agS = fmaf(-TL2E2, rcpf(1.f + ex2f(zg)), TL2E);
            c = fmaf(af, c, ai * agS);                 /* c' = TL2E*c_true */
            h = ao * fmaf(-2.f, rcpf(1.f + ex2f(c)), 1.f);

            s_h[w][(tt & 1) ^ 1][j] = h;
            __syncwarp();
        }
    }

    float v = fc_w[j] * h;
    #pragma unroll
    for (int off = 16; off; off >>= 1)
        v += __shfl_down_sync(0xffffffffu, v, off);
    if (j == 0) out[b] = v + fc_b[0];
}

/* ======================================================================== */
extern "C" void kernel_launch(void* const* d_in, const int* in_sizes, int n_in,
                              void* d_out, int out_size)
{
    const float* x      = (const float*)d_in[0];
    const float* conv_w = (const float*)d_in[1];
    const float* conv_b = (const float*)d_in[2];
    const float* w_ih   = (const float*)d_in[3];
    const float* w_hh   = (const float*)d_in[4];
    const float* b_ih   = (const float*)d_in[5];
    const float* b_hh   = (const float*)d_in[6];
    const float* fc_w   = (const float*)d_in[7];
    const float* fc_b   = (const float*)d_in[8];
    float* out = (float*)d_out;

    precompute_L_kernel<<<1, 64>>>();
    precompute_fold_kernel<<<NCH, 32>>>(conv_w);

    size_t smem_f = (size_t)SM_TOTAL_U64 * sizeof(u64t);
    cudaFuncSetAttribute(fused_kernel,
                         cudaFuncAttributeMaxDynamicSharedMemorySize, (int)smem_f);
    fused_kernel<<<B_SZ * 4, 512, smem_f>>>(x, conv_b, w_ih, b_ih, b_hh);

    lstm5_kernel<<<B_SZ / 2, 64>>>(w_hh, fc_w, fc_b, out);
}

// round 11
// speedup vs baseline: 1.5472x; 1.0334x over previous
#include <cuda_runtime.h>
#include <math.h>

#define B_SZ     256
#define S_LEN    1024
#define T_LEN    21
#define NFREQ    11
#define NCH      32
#define COUT     64
#define POOL_T   512
#define HID      32
#define NWROWS   46
#define FPITCH   264     /* feature tile pitch in floats */
#define FROWP    132     /* sP pitch in floats */

#define L2E    1.4426950408889634f
#define TL2E   2.8853900817779268f
#define TL2E2  5.7707801635558537f

typedef unsigned long long u64t;

/* ---------------- device scratch (module-static, no runtime alloc) ------ */
__device__ __align__(16) float g_tw[T_LEN * NFREQ * 2];
__device__ __align__(16) float g_L[NWROWS * T_LEN];
__device__ __align__(16) ulonglong2 g_w01[NCH * 32];
__device__ __align__(16) u64t g_w2v[NCH * 32];
__device__ __align__(16) float g_xg[B_SZ * POOL_T * 128];

__constant__ float c_lo[8] = {
    -0.010597401784997278f,  0.032883011666982945f,  0.030841381835986965f,
    -0.18703481171888114f,  -0.02798376941698385f,   0.6308807679295904f,
     0.7148465705525415f,    0.23037781330885523f };
__constant__ float c_hi[8] = {
    -0.23037781330885523f,   0.7148465705525415f,   -0.6308807679295904f,
    -0.02798376941698385f,   0.18703481171888114f,   0.030841381835986965f,
    -0.032883011666982945f, -0.010597401784997278f };

/* ---------------- packed f32x2 + fast-math helpers ---------------------- */
static __device__ __forceinline__ u64t pk2(float a, float b) {
    u64t r;
    asm("mov.b64 %0,{%1,%2};" : "=l"(r) : "f"(a), "f"(b));
    return r;
}
static __device__ __forceinline__ void upk2(u64t v, float& a, float& b) {
    asm("mov.b64 {%0,%1},%2;" : "=f"(a), "=f"(b) : "l"(v));
}
static __device__ __forceinline__ void ffma2(u64t& d, u64t a, u64t b) {
    asm("fma.rn.f32x2 %0,%1,%2,%0;" : "+l"(d) : "l"(a), "l"(b));
}
static __device__ __forceinline__ void fadd2(u64t& d, u64t a) {
    asm("add.rn.f32x2 %0,%0,%1;" : "+l"(d) : "l"(a));
}
static __device__ __forceinline__ float ex2f(float x) {
    float r; asm("ex2.approx.f32 %0,%1;" : "=f"(r) : "f"(x)); return r;
}
static __device__ __forceinline__ float rcpf(float x) {
    float r; asm("rcp.approx.f32 %0,%1;" : "=f"(r) : "f"(x)); return r;
}
static __device__ __forceinline__ float sig_p(float zp) {
    return rcpf(1.f + ex2f(-zp));
}

/* ============ K0a: twiddles + wavelet linear map L (tiny, 1 block) ======= */
__global__ void precompute_L_kernel()
{
    int tid = threadIdx.x;

    for (int i = tid; i < T_LEN * NFREQ; i += blockDim.x) {
        int n = i / NFREQ, k = i % NFREQ;
        double ang = 2.0 * (double)(k * n) / 21.0;
        g_tw[2 * i]     = (float)cospi(ang);
        g_tw[2 * i + 1] = (float)(-sinpi(ang));
    }

    if (tid < T_LEN) {
        float a[21];
        #pragma unroll
        for (int i = 0; i < 21; i++) a[i] = (i == tid) ? 1.f : 0.f;
        int n = 21;
        const int rowbase[4] = {32, 22, 14, 7};
        for (int lev = 0; lev < 4; lev++) {
            int mout = (n + 5) / 2 + 1;
            float cA[14];
            for (int m = 0; m < mout; m++) {
                float aL = 0.f, aH = 0.f;
                #pragma unroll
                for (int j = 0; j < 8; j++) {
                    int idx = 2 * m + 1 - j;
                    if (idx < 0)  idx = -idx - 1;
                    if (idx >= n) idx = 2 * n - 1 - idx;
                    aL += c_lo[j] * a[idx];
                    aH += c_hi[j] * a[idx];
                }
                cA[m] = aL;
                g_L[(rowbase[lev] + m) * T_LEN + tid] = aH;
            }
            for (int m = 0; m < mout; m++) a[m] = cA[m];
            n = mout;
        }
        for (int m = 0; m < n; m++)
            g_L[m * T_LEN + tid] = a[m];
    }
}

/* ============ K0b: weight fold, grid 32 (ci) x 32 threads (cp) =========== */
__global__ void __launch_bounds__(32) precompute_fold_kernel(
    const float* __restrict__ conv_w)
{
    __shared__ float sL[NWROWS];

    int ci = blockIdx.x;
    int cp = threadIdx.x;

    if (ci < T_LEN) {
        for (int j = cp; j < NWROWS; j += 32)
            sL[j] = g_L[j * T_LEN + ci];
    }
    __syncwarp();

    float vlo[3], vhi[3];
    #pragma unroll
    for (int k = 0; k < 3; k++) {
        vlo[k] = conv_w[(cp * 78 + ci) * 3 + k];
        vhi[k] = conv_w[((cp + 32) * 78 + ci) * 3 + k];
    }
    if (ci < T_LEN) {
        const float* wl = conv_w + (cp * 78 + 32) * 3;
        const float* wh = conv_w + ((cp + 32) * 78 + 32) * 3;
        #pragma unroll 2
        for (int j = 0; j < NWROWS; j++) {
            float l = sL[j];
            #pragma unroll
            for (int k = 0; k < 3; k++) {
                vlo[k] = fmaf(wl[j * 3 + k], l, vlo[k]);
                vhi[k] = fmaf(wh[j * 3 + k], l, vhi[k]);
            }
        }
    }
    ulonglong2 w01;
    w01.x = pk2(vlo[0], vhi[0]);
    w01.y = pk2(vlo[1], vhi[1]);
    g_w01[ci * 32 + cp] = w01;
    g_w2v[ci * 32 + cp] = pk2(vlo[2], vhi[2]);
}

/* ============ K1: fused feat(DFT) + conv3/ReLU/maxpool2 + xg GEMM ======== */
/* smem (u64 units):
   sfeat [0, 4224)       : 32ch x 264 plain floats
   sw01  [4224, 6272)    : conv taps k0,k1
   sw2v  [6272, 7296)    : conv tap k2
   sW    [7296, 11520)   : xg weights [k=64][pitch 66]
   sP    [11520, 15744)  : pooled tile floats [k=64][pitch 132]
   stw   [15744, 15976)  : DFT twiddles                                     */
#define SM_SW01  4224
#define SM_SW2V  6272
#define SM_SW    7296
#define SM_SP    11520
#define SM_STW   15744
#define SM_TOTAL_U64 15976

__global__ void __launch_bounds__(512) fused_kernel(
    const float* __restrict__ x,   const float* __restrict__ conv_b,
    const float* __restrict__ w_ih, const float* __restrict__ b_ih,
    const float* __restrict__ b_hh)
{
    extern __shared__ u64t sm[];
    float*      sfeat = (float*)sm;
    ulonglong2* sw01  = (ulonglong2*)(sm + SM_SW01);
    u64t*       sw2v  = sm + SM_SW2V;
    u64t*       sW    = sm + SM_SW;
    float*      sP    = (float*)(sm + SM_SP);
    float*      stw   = (float*)(sm + SM_STW);

    int tid = threadIdx.x;
    int b   = blockIdx.x >> 2;
    int q   = blockIdx.x & 3;
    int s0  = q * 256;

    /* ---- phase 0: stage all weights/twiddles ---- */
    for (int i = tid; i < NCH * 32; i += 512) {
        sw01[i] = g_w01[i];
        sw2v[i] = g_w2v[i];
    }
    for (int i = tid; i < T_LEN * NFREQ * 2; i += 512)
        stw[i] = g_tw[i];
    for (int idx = tid; idx < 64 * 64; idx += 512) {
        int k = idx >> 6, cp = idx & 63;
        int j = cp >> 1, g0 = (cp & 1) * 2;
        float s0f = (cp & 1) ? TL2E : L2E;
        sW[k * 66 + cp] = pk2(w_ih[(g0 * 32 + j) * 64 + k] * s0f,
                              w_ih[((g0 + 1) * 32 + j) * 64 + k] * L2E);
    }
    __syncthreads();

    /* ---- phase 1: features, all 512 threads ----
       group A (tid<258): col=tid, raw rows 0..20 + freqs 0..5
       group B (tid>=258): col=tid-254 (4..257), freqs 6..10
       tids 0..3 also cover freqs 6..10 for cols 0..3                        */
    {
        bool isA = (tid < 258);
        int col  = isA ? tid : (tid - 254);
        int s    = s0 + col - 1;
        if (s >= 0 && s < S_LEN) {
            const float* xp = x + (size_t)(b * S_LEN + s) * T_LEN;
            float xr[T_LEN];
            #pragma unroll
            for (int i = 0; i < T_LEN; i++) xr[i] = xp[i];

            if (isA) {
                #pragma unroll
                for (int i = 0; i < T_LEN; i++)
                    sfeat[i * FPITCH + col] = xr[i];
                #pragma unroll
                for (int k = 0; k < 6; k++) {
                    float re = 0.f, im = 0.f;
                    #pragma unroll
                    for (int n = 0; n < T_LEN; n++) {
                        re = fmaf(xr[n], stw[(n * NFREQ + k) * 2],     re);
                        im = fmaf(xr[n], stw[(n * NFREQ + k) * 2 + 1], im);
                    }
                    sfeat[(T_LEN + k) * FPITCH + col] = sqrtf(re * re + im * im);
                }
            }
            if (!isA || tid < 4) {
                #pragma unroll
                for (int k = 6; k < NFREQ; k++) {
                    float re = 0.f, im = 0.f;
                    #pragma unroll
                    for (int n = 0; n < T_LEN; n++) {
                        re = fmaf(xr[n], stw[(n * NFREQ + k) * 2],     re);
                        im = fmaf(xr[n], stw[(n * NFREQ + k) * 2 + 1], im);
                    }
                    sfeat[(T_LEN + k) * FPITCH + col] = sqrtf(re * re + im * im);
                }
            }
        } else {
            if (isA) {
                #pragma unroll
                for (int ci = 0; ci < NCH; ci++)
                    sfeat[ci * FPITCH + col] = 0.f;
            } else {
                #pragma unroll
                for (int k = 6; k < NFREQ; k++)
                    sfeat[(T_LEN + k) * FPITCH + col] = 0.f;
            }
        }
    }
    __syncthreads();

    /* ---- phase 2: conv3 + ReLU + maxpool2 -> sP[k][t] (transposed) ----
       Non-dup smem reads (5 LDS vs 9); dup pairs built in registers.       */
    {
        int cp = tid & 31;
        int sg = tid >> 5;
        int cs = sg * 16;

        u64t bias2 = pk2(conv_b[cp], conv_b[cp + 32]);
        u64t acc[16];
        #pragma unroll
        for (int i = 0; i < 16; i++) acc[i] = bias2;

        for (int ci = 0; ci < NCH; ci++) {
            const float* vpf = sfeat + ci * FPITCH + cs;
            float4 f0 = *(const float4*)(vpf);
            float4 f1 = *(const float4*)(vpf + 4);
            float4 f2 = *(const float4*)(vpf + 8);
            float4 f3 = *(const float4*)(vpf + 12);
            float2 f4 = *(const float2*)(vpf + 16);
            float vv[18] = { f0.x, f0.y, f0.z, f0.w, f1.x, f1.y, f1.z, f1.w,
                             f2.x, f2.y, f2.z, f2.w, f3.x, f3.y, f3.z, f3.w,
                             f4.x, f4.y };
            u64t v[18];
            #pragma unroll
            for (int i = 0; i < 18; i++) v[i] = pk2(vv[i], vv[i]);

            ulonglong2 w01 = sw01[ci * 32 + cp];
            u64t       wk2 = sw2v[ci * 32 + cp];
            #pragma unroll
            for (int i = 0; i < 16; i++) {
                ffma2(acc[i], w01.x, v[i]);
                ffma2(acc[i], w01.y, v[i + 1]);
                ffma2(acc[i], wk2,   v[i + 2]);
            }
        }

        int t0l = sg * 8;
        #pragma unroll
        for (int i = 0; i < 8; i++) {
            float l0, h0, l1, h1;
            upk2(acc[2 * i],     l0, h0);
            upk2(acc[2 * i + 1], l1, h1);
            sP[cp * FROWP + t0l + i]        = fmaxf(fmaxf(l0, l1), 0.f);
            sP[(cp + 32) * FROWP + t0l + i] = fmaxf(fmaxf(h0, h1), 0.f);
        }
    }
    __syncthreads();

    /* ---- phase 3: xg GEMM, 256 threads, 8-row x 4-colpair tiles -------- */
    if (tid < 256) {
        int tx = tid & 15, ty = tid >> 4;
        int r0 = ty * 8;

        u64t acc[8][4];
        #pragma unroll
        for (int i = 0; i < 8; i++)
            #pragma unroll
            for (int qq = 0; qq < 4; qq++) acc[i][qq] = 0ull;

        #pragma unroll 4
        for (int k = 0; k < 64; k++) {
            const float* ar = sP + k * FROWP + r0;
            float4 av0 = *(const float4*)ar;
            float4 av1 = *(const float4*)(ar + 4);
            u64t ad[8] = { pk2(av0.x, av0.x), pk2(av0.y, av0.y),
                           pk2(av0.z, av0.z), pk2(av0.w, av0.w),
                           pk2(av1.x, av1.x), pk2(av1.y, av1.y),
                           pk2(av1.z, av1.z), pk2(av1.w, av1.w) };
            const u64t* wr = sW + k * 66 + tx;
            u64t wv[4] = { wr[0], wr[16], wr[32], wr[48] };
            #pragma unroll
            for (int i = 0; i < 8; i++)
                #pragma unroll
                for (int qq = 0; qq < 4; qq++)
                    ffma2(acc[i][qq], ad[i], wv[qq]);
        }

        float* outp = g_xg + ((size_t)b * POOL_T + q * 128) * 128;
        #pragma unroll
        for (int qq = 0; qq < 4; qq++) {
            int cp = tx + qq * 16;
            int j = cp >> 1, g0 = (cp & 1) * 2;
            int gi0 = g0 * 32 + j, gi1 = (g0 + 1) * 32 + j;
            float s0f = (cp & 1) ? TL2E : L2E;
            u64t bp = pk2((b_ih[gi0] + b_hh[gi0]) * s0f,
                          (b_ih[gi1] + b_hh[gi1]) * L2E);
            #pragma unroll
            for (int i = 0; i < 8; i++) {
                u64t s = acc[i][qq];
                fadd2(s, bp);
                float lo, hi;
                upk2(s, lo, hi);
                *(float2*)(outp + (size_t)(r0 + i) * 128 + cp * 2) = make_float2(lo, hi);
            }
        }
    }
}

/* ============ K3: LSTM v5.1 (best known recurrence) ====================== */
__global__ void __launch_bounds__(64) lstm5_kernel(
    const float* __restrict__ w_hh, const float* __restrict__ fc_w,
    const float* __restrict__ fc_b, float* __restrict__ out)
{
    __shared__ __align__(16) float s_h[2][2][32];

    int w = threadIdx.x >> 5;
    int j = threadIdx.x & 31;
    int b = blockIdx.x * 2 + w;

    const float sc[4] = { L2E, L2E, TL2E, L2E };
    u64t w2[4][16];
    #pragma unroll
    for (int g = 0; g < 4; g++) {
        const float4* row = (const float4*)(w_hh + (g * 32 + j) * 32);
        #pragma unroll
        for (int q = 0; q < 8; q++) {
            float4 v = row[q];
            w2[g][2 * q]     = pk2(v.x * sc[g], v.y * sc[g]);
            w2[g][2 * q + 1] = pk2(v.z * sc[g], v.w * sc[g]);
        }
    }

    s_h[w][0][j] = 0.f;
    float c = 0.f, h = 0.f;

    const ulonglong2* xgp = (const ulonglong2*)(g_xg + (size_t)b * POOL_T * 128);
    ulonglong2 pre[4];
    #pragma unroll
    for (int u = 0; u < 4; u++) pre[u] = xgp[u * 32 + j];
    __syncwarp();

    for (int t = 0; t < POOL_T; t += 4) {
        #pragma unroll
        for (int u = 0; u < 4; u++) {
            int tt = t + u;
            ulonglong2 z4 = pre[u];
            int tn = tt + 4;
            if (tn > POOL_T - 1) tn = POOL_T - 1;
            pre[u] = xgp[(size_t)tn * 32 + j];

            const ulonglong2* hp = (const ulonglong2*)s_h[w][tt & 1];

            u64t a0 = z4.x & 0xffffffffull, a1 = z4.x >> 32;
            u64t a2 = z4.y & 0xffffffffull, a3 = z4.y >> 32;
            u64t b0 = 0, b1 = 0, b2 = 0, b3 = 0;
            u64t d0 = 0, d1 = 0, d2 = 0, d3 = 0;
            u64t e0 = 0, e1 = 0, e2 = 0, e3 = 0;

            #pragma unroll
            for (int kq = 0; kq < 4; kq++) {
                ulonglong2 h2 = hp[kq];
                ffma2(a0, w2[0][2 * kq], h2.x);
                ffma2(a1, w2[1][2 * kq], h2.x);
                ffma2(a2, w2[2][2 * kq], h2.x);
                ffma2(a3, w2[3][2 * kq], h2.x);
                ffma2(d0, w2[0][2 * kq + 1], h2.y);
                ffma2(d1, w2[1][2 * kq + 1], h2.y);
                ffma2(d2, w2[2][2 * kq + 1], h2.y);
                ffma2(d3, w2[3][2 * kq + 1], h2.y);
            }
            #pragma unroll
            for (int kq = 4; kq < 8; kq++) {
                ulonglong2 h2 = hp[kq];
                ffma2(b0, w2[0][2 * kq], h2.x);
                ffma2(b1, w2[1][2 * kq], h2.x);
                ffma2(b2, w2[2][2 * kq], h2.x);
                ffma2(b3, w2[3][2 * kq], h2.x);
                ffma2(e0, w2[0][2 * kq + 1], h2.y);
                ffma2(e1, w2[1][2 * kq + 1], h2.y);
                ffma2(e2, w2[2][2 * kq + 1], h2.y);
                ffma2(e3, w2[3][2 * kq + 1], h2.y);
            }
            fadd2(a0, b0); fadd2(d0, e0); fadd2(a0, d0);
            fadd2(a1, b1); fadd2(d1, e1); fadd2(a1, d1);
            fadd2(a2, b2); fadd2(d2, e2); fadd2(a2, d2);
            fadd2(a3, b3); fadd2(d3, e3); fadd2(a3, d3);

            float lo, hi;
            upk2(a0, lo, hi); float zi = lo + hi;
            upk2(a1, lo, hi); float zf = lo + hi;
            upk2(a2, lo, hi); float zg = lo + hi;
            upk2(a3, lo, hi); float zo = lo + hi;

            float ai = sig_p(zi), af = sig_p(zf);
            float ao = sig_p(zo);
            float agS = fmaf(-TL2E2, rcpf(1.f + ex2f(zg)), TL2E);
            c = fmaf(af, c, ai * agS);
            h = ao * fmaf(-2.f, rcpf(1.f + ex2f(c)), 1.f);

            s_h[w][(tt & 1) ^ 1][j] = h;
            __syncwarp();
        }
    }

    float v = fc_w[j] * h;
    #pragma unroll
    for (int off = 16; off; off >>= 1)
        v += __shfl_down_sync(0xffffffffu, v, off);
    if (j == 0) out[b] = v + fc_b[0];
}

/* ======================================================================== */
extern "C" void kernel_launch(void* const* d_in, const int* in_sizes, int n_in,
                              void* d_out, int out_size)
{
    const float* x      = (const float*)d_in[0];
    const float* conv_w = (const float*)d_in[1];
    const float* conv_b = (const float*)d_in[2];
    const float* w_ih   = (const float*)d_in[3];
    const float* w_hh   = (const float*)d_in[4];
    const float* b_ih   = (const float*)d_in[5];
    const float* b_hh   = (const float*)d_in[6];
    const float* fc_w   = (const float*)d_in[7];
    const float* fc_b   = (const float*)d_in[8];
    float* out = (float*)d_out;

    precompute_L_kernel<<<1, 64>>>();
    precompute_fold_kernel<<<NCH, 32>>>(conv_w);

    size_t smem_f = (size_t)SM_TOTAL_U64 * sizeof(u64t);
    cudaFuncSetAttribute(fused_kernel,
                         cudaFuncAttributeMaxDynamicSharedMemorySize, (int)smem_f);
    fused_kernel<<<B_SZ * 4, 512, smem_f>>>(x, conv_b, w_ih, b_ih, b_hh);

    lstm5_kernel<<<B_SZ / 2, 64>>>(w_hh, fc_w, fc_b, out);
}